// round 16
// baseline (speedup 1.0000x reference)
#include <cuda_runtime.h>
#include <cuda_fp16.h>

#define NN   50000
#define ER   1600000
#define EMB  32
#define HID  128
#define TILE 64
#define CAP  128          // bucket capacity per node (E[deg]=32, P(>128)~1e-40)
#define OVMAX 8192
#define FULL 0xffffffffu

typedef unsigned long long u64;

// ---- packed f32x2 helpers (sm_103a FFMA2 path, PTX-only) ----
__device__ __forceinline__ u64 dup2(float a) {
    u64 r; asm("mov.b64 %0, {%1, %1};" : "=l"(r) : "f"(a)); return r;
}
__device__ __forceinline__ u64 packf2(float a, float b) {
    u64 r; asm("mov.b64 %0, {%1, %2};" : "=l"(r) : "f"(a), "f"(b)); return r;
}
__device__ __forceinline__ void ffma2(u64& d, u64 a, u64 b) {
    asm("fma.rn.f32x2 %0, %1, %2, %0;" : "+l"(d) : "l"(a), "l"(b));
}
__device__ __forceinline__ float2 unpackf2(u64 v) {
    float2 r; asm("mov.b64 {%0, %1}, %2;" : "=f"(r.x), "=f"(r.y) : "l"(v)); return r;
}

// ---------------- device scratch (static, no cudaMalloc; 16B-aligned for LDG.128) ----------------
__device__ int    g_cursor[NN];
__device__ float  g_dinv[NN];
__device__ __align__(16) int    g_col[NN * CAP];     // 25.6 MB direct buckets
__device__ int    g_ovcnt;
__device__ int2   g_ov[OVMAX];
__device__ __align__(16) __half g_xsh[NN * EMB];     //  3.2 MB  (fp16 dinv-scaled emb)
__device__ __align__(16) float  g_aggemb[NN * EMB];  //  6.4 MB
__device__ __align__(16) __half g_h1h[NN * HID];     // 12.8 MB  (fp16 dinv-scaled hidden)
__device__ __align__(16) __half g_agg2h[NN * HID];   // 12.8 MB  (fp16 layer-2 aggregate)

// ---------------- 1) init ----------------
__global__ void k_init() {
    int i = blockIdx.x * 256 + threadIdx.x;
    if (i < NN) g_cursor[i] = 0;
    if (i == 0) g_ovcnt = 0;
}

// ---------------- 2) direct-bucket scatter (8 edges/thread, MLP=8) ----------------
__global__ void k_scatter(const int* __restrict__ ei) {
    int t = blockIdx.x * 256 + threadIdx.x;          // t < ER/8
    if (t >= ER / 8) return;
    int4 sa = reinterpret_cast<const int4*>(ei)[2 * t];
    int4 sb = reinterpret_cast<const int4*>(ei)[2 * t + 1];
    int4 da = reinterpret_cast<const int4*>(ei + ER)[2 * t];
    int4 db = reinterpret_cast<const int4*>(ei + ER)[2 * t + 1];
    int p0 = atomicAdd(&g_cursor[da.x], 1);
    int p1 = atomicAdd(&g_cursor[da.y], 1);
    int p2 = atomicAdd(&g_cursor[da.z], 1);
    int p3 = atomicAdd(&g_cursor[da.w], 1);
    int p4 = atomicAdd(&g_cursor[db.x], 1);
    int p5 = atomicAdd(&g_cursor[db.y], 1);
    int p6 = atomicAdd(&g_cursor[db.z], 1);
    int p7 = atomicAdd(&g_cursor[db.w], 1);
#define PUT(p, d, s) \
    if ((p) < CAP) g_col[(d) * CAP + (p)] = (s); \
    else { int o = atomicAdd(&g_ovcnt, 1); if (o < OVMAX) g_ov[o] = make_int2((d), (s)); }
    PUT(p0, da.x, sa.x) PUT(p1, da.y, sa.y) PUT(p2, da.z, sa.z) PUT(p3, da.w, sa.w)
    PUT(p4, db.x, sb.x) PUT(p5, db.y, sb.y) PUT(p6, db.z, sb.z) PUT(p7, db.w, sb.w)
#undef PUT
}

// ---------------- 3) fused dinv + xsh = fp16(dinv * emb) ----------------
__global__ void k_dinv_scale(const float* __restrict__ emb) {
    int t = blockIdx.x * 256 + threadIdx.x;          // t < NN*8 (float4 per thread)
    if (t >= NN * (EMB / 4)) return;
    int n = t >> 3;
    float d = rsqrtf((float)(g_cursor[n] + 1));      // +1 self loop
    if ((t & 7) == 0) g_dinv[n] = d;
    float4 v = reinterpret_cast<const float4*>(emb)[t];
    __half2 h0 = __floats2half2_rn(v.x * d, v.y * d);
    __half2 h1 = __floats2half2_rn(v.z * d, v.w * d);
    uint2 st;
    st.x = *reinterpret_cast<unsigned*>(&h0);
    st.y = *reinterpret_cast<unsigned*>(&h1);
    reinterpret_cast<uint2*>(g_xsh)[t] = st;
}

// ---------------- 4) aggregate embeddings: fp16 HADD2 accumulate, flush per block ----------------
// lane = 4*g + l : group g in [0,8) handles edge jb+g; sublane l in [0,4) owns dims [8l, 8l+8).
__global__ void __launch_bounds__(256) k_agg_emb() {
    int w    = (blockIdx.x * 256 + threadIdx.x) >> 5;
    int lane = threadIdx.x & 31;
    int g    = lane >> 2;
    int l    = lane & 3;
    float di = g_dinv[w];
    float a0 = 0.f, a1 = 0.f, a2 = 0.f, a3 = 0.f,
          a4 = 0.f, a5 = 0.f, a6 = 0.f, a7 = 0.f;
    int cnt = min(g_cursor[w], CAP);
    const int* cb = g_col + w * CAP;
    const uint4* xv = reinterpret_cast<const uint4*>(g_xsh);   // 8 halves / uint4, 4 per row
    const __half2 hz = __float2half2_rn(0.f);
    for (int base = 0; base < cnt; base += 32) {
        int c = cb[base + lane];                     // coalesced 128B
        int m = min(32, cnt - base);                 // warp-uniform
        __half2 h0 = hz, h1 = hz, h2 = hz, h3 = hz;  // <=4-term fp16 chains
        if (m == 32) {
#pragma unroll
            for (int jb = 0; jb < 32; jb += 8) {
                int   s = __shfl_sync(FULL, c, jb + g);        // per-lane source
                uint4 u = xv[s * 4 + l];
                h0 = __hadd2(h0, *reinterpret_cast<__half2*>(&u.x));
                h1 = __hadd2(h1, *reinterpret_cast<__half2*>(&u.y));
                h2 = __hadd2(h2, *reinterpret_cast<__half2*>(&u.z));
                h3 = __hadd2(h3, *reinterpret_cast<__half2*>(&u.w));
            }
        } else {
            for (int jb = 0; jb < m; jb += 8) {
                int  j   = jb + g;
                bool act = (j < m);
                int  s   = __shfl_sync(FULL, c, act ? j : 0);
                uint4 u  = xv[s * 4 + l];
                if (act) {
                    h0 = __hadd2(h0, *reinterpret_cast<__half2*>(&u.x));
                    h1 = __hadd2(h1, *reinterpret_cast<__half2*>(&u.y));
                    h2 = __hadd2(h2, *reinterpret_cast<__half2*>(&u.z));
                    h3 = __hadd2(h3, *reinterpret_cast<__half2*>(&u.w));
                }
            }
        }
        float2 f0 = __half22float2(h0);
        float2 f1 = __half22float2(h1);
        float2 f2 = __half22float2(h2);
        float2 f3 = __half22float2(h3);
        a0 += f0.x; a1 += f0.y; a2 += f1.x; a3 += f1.y;
        a4 += f2.x; a5 += f2.y; a6 += f3.x; a7 += f3.y;
    }
    // reduce across the 8 groups (lanes differing in bits 2,3,4)
#pragma unroll
    for (int off = 4; off <= 16; off <<= 1) {
        a0 += __shfl_xor_sync(FULL, a0, off);
        a1 += __shfl_xor_sync(FULL, a1, off);
        a2 += __shfl_xor_sync(FULL, a2, off);
        a3 += __shfl_xor_sync(FULL, a3, off);
        a4 += __shfl_xor_sync(FULL, a4, off);
        a5 += __shfl_xor_sync(FULL, a5, off);
        a6 += __shfl_xor_sync(FULL, a6, off);
        a7 += __shfl_xor_sync(FULL, a7, off);
    }
    if (g == 0) {
        uint4 u = xv[w * 4 + l];                     // self loop
        float2 f0 = __half22float2(*reinterpret_cast<__half2*>(&u.x));
        float2 f1 = __half22float2(*reinterpret_cast<__half2*>(&u.y));
        float2 f2 = __half22float2(*reinterpret_cast<__half2*>(&u.z));
        float2 f3 = __half22float2(*reinterpret_cast<__half2*>(&u.w));
        a0 = (a0 + f0.x) * di; a1 = (a1 + f0.y) * di;
        a2 = (a2 + f1.x) * di; a3 = (a3 + f1.y) * di;
        a4 = (a4 + f2.x) * di; a5 = (a5 + f2.y) * di;
        a6 = (a6 + f3.x) * di; a7 = (a7 + f3.y) * di;
        float4* dst = reinterpret_cast<float4*>(&g_aggemb[w * EMB + l * 8]);
        dst[0] = make_float4(a0, a1, a2, a3);
        dst[1] = make_float4(a4, a5, a6, a7);
    }
}

// ---------------- 4b) overflow fallback for layer-1 agg (normally empty) ----------------
__global__ void k_ovf1() {
    int nov = min(g_ovcnt, OVMAX);
    int lane = threadIdx.x & 31;
    int warp = (blockIdx.x * 256 + threadIdx.x) >> 5;
    int nw   = (gridDim.x * 256) >> 5;
    for (int i = warp; i < nov; i += nw) {
        int2 e = g_ov[i];                            // (dst, src)
        float v = __half2float(g_xsh[e.y * EMB + lane]);
        atomicAdd(&g_aggemb[e.x * EMB + lane], v * g_dinv[e.x]);
    }
}

// ---------------- 5) GEMM1: h1s = dinv * relu(aggemb @ W1 + b1) -> fp16 ----------------
__global__ void __launch_bounds__(256) k_gemm1(const float* __restrict__ W1,
                                               const float* __restrict__ b1) {
    __shared__ float As[TILE * EMB];     // 8 KB
    int tid  = threadIdx.x;
    int tcol = (tid & 15) * 8;
    int trow = (tid >> 4) * 4;
    int row0 = blockIdx.x * TILE;
    u64 bias[4];
    bias[0] = packf2(__ldg(&b1[tcol]),     __ldg(&b1[tcol + 1]));
    bias[1] = packf2(__ldg(&b1[tcol + 2]), __ldg(&b1[tcol + 3]));
    bias[2] = packf2(__ldg(&b1[tcol + 4]), __ldg(&b1[tcol + 5]));
    bias[3] = packf2(__ldg(&b1[tcol + 6]), __ldg(&b1[tcol + 7]));

#pragma unroll
    for (int i = 0; i < 2; i++) {
        int idx = tid + i * 256;
        int gr  = row0 + (idx >> 3);
        reinterpret_cast<float4*>(As)[idx] = (gr < NN)
            ? reinterpret_cast<const float4*>(g_aggemb)[gr * 8 + (idx & 7)]
            : make_float4(0.f, 0.f, 0.f, 0.f);
    }
    __syncthreads();

    u64 acc[4][4];
#pragma unroll
    for (int r = 0; r < 4; r++)
#pragma unroll
        for (int c = 0; c < 4; c++) acc[r][c] = bias[c];
#pragma unroll
    for (int k = 0; k < EMB; k++) {
        ulonglong2 wa = __ldg(reinterpret_cast<const ulonglong2*>(&W1[k * HID + tcol]));
        ulonglong2 wb = __ldg(reinterpret_cast<const ulonglong2*>(&W1[k * HID + tcol + 4]));
#pragma unroll
        for (int r = 0; r < 4; r++) {
            u64 a = dup2(As[(trow + r) * EMB + k]);
            ffma2(acc[r][0], a, wa.x); ffma2(acc[r][1], a, wa.y);
            ffma2(acc[r][2], a, wb.x); ffma2(acc[r][3], a, wb.y);
        }
    }
#pragma unroll
    for (int r = 0; r < 4; r++) {
        int gr = row0 + trow + r;
        if (gr < NN) {
            float d = g_dinv[gr];
            float2 p0 = unpackf2(acc[r][0]);
            float2 p1 = unpackf2(acc[r][1]);
            float2 p2 = unpackf2(acc[r][2]);
            float2 p3 = unpackf2(acc[r][3]);
            __half2 h0 = __floats2half2_rn(fmaxf(p0.x, 0.f) * d, fmaxf(p0.y, 0.f) * d);
            __half2 h1 = __floats2half2_rn(fmaxf(p1.x, 0.f) * d, fmaxf(p1.y, 0.f) * d);
            __half2 h2 = __floats2half2_rn(fmaxf(p2.x, 0.f) * d, fmaxf(p2.y, 0.f) * d);
            __half2 h3 = __floats2half2_rn(fmaxf(p3.x, 0.f) * d, fmaxf(p3.y, 0.f) * d);
            uint4 st;
            st.x = *reinterpret_cast<unsigned*>(&h0);
            st.y = *reinterpret_cast<unsigned*>(&h1);
            st.z = *reinterpret_cast<unsigned*>(&h2);
            st.w = *reinterpret_cast<unsigned*>(&h3);
            *reinterpret_cast<uint4*>(&g_h1h[gr * HID + tcol]) = st;
        }
    }
}

// ---------------- 6) aggregate h1s: fp16 gather, fp32 accumulate, 2 edges in flight ----------------
// lane = 16*g + l : group g handles edge jb+g; sublane l owns dims [8l, 8l+8).
__global__ void __launch_bounds__(256) k_agg_h1() {
    int w    = (blockIdx.x * 256 + threadIdx.x) >> 5;
    int lane = threadIdx.x & 31;
    int g    = lane >> 4;
    int l    = lane & 15;
    float di = g_dinv[w];
    float a0 = 0.f, a1 = 0.f, a2 = 0.f, a3 = 0.f,
          a4 = 0.f, a5 = 0.f, a6 = 0.f, a7 = 0.f;
    int cnt = min(g_cursor[w], CAP);
    const int* cb = g_col + w * CAP;
    const uint4* hv = reinterpret_cast<const uint4*>(g_h1h);   // 8 halves / uint4
    for (int base = 0; base < cnt; base += 32) {
        int c = cb[base + lane];
        int m = min(32, cnt - base);                 // warp-uniform
        if (m == 32) {
#pragma unroll 4
            for (int jb = 0; jb < 32; jb += 2) {
                int   s = __shfl_sync(FULL, c, jb + g);
                uint4 u = hv[s * 16 + l];
                float2 f0 = __half22float2(*reinterpret_cast<__half2*>(&u.x));
                float2 f1 = __half22float2(*reinterpret_cast<__half2*>(&u.y));
                float2 f2 = __half22float2(*reinterpret_cast<__half2*>(&u.z));
                float2 f3 = __half22float2(*reinterpret_cast<__half2*>(&u.w));
                a0 += f0.x; a1 += f0.y; a2 += f1.x; a3 += f1.y;
                a4 += f2.x; a5 += f2.y; a6 += f3.x; a7 += f3.y;
            }
        } else {
            for (int jb = 0; jb < m; jb += 2) {
                int  j   = jb + g;
                bool act = (j < m);
                int  s   = __shfl_sync(FULL, c, act ? j : 0);
                uint4 u  = hv[s * 16 + l];
                float2 f0 = __half22float2(*reinterpret_cast<__half2*>(&u.x));
                float2 f1 = __half22float2(*reinterpret_cast<__half2*>(&u.y));
                float2 f2 = __half22float2(*reinterpret_cast<__half2*>(&u.z));
                float2 f3 = __half22float2(*reinterpret_cast<__half2*>(&u.w));
                if (act) {
                    a0 += f0.x; a1 += f0.y; a2 += f1.x; a3 += f1.y;
                    a4 += f2.x; a5 += f2.y; a6 += f3.x; a7 += f3.y;
                }
            }
        }
    }
    a0 += __shfl_xor_sync(FULL, a0, 16);
    a1 += __shfl_xor_sync(FULL, a1, 16);
    a2 += __shfl_xor_sync(FULL, a2, 16);
    a3 += __shfl_xor_sync(FULL, a3, 16);
    a4 += __shfl_xor_sync(FULL, a4, 16);
    a5 += __shfl_xor_sync(FULL, a5, 16);
    a6 += __shfl_xor_sync(FULL, a6, 16);
    a7 += __shfl_xor_sync(FULL, a7, 16);
    if (g == 0) {
        uint4 u = hv[w * 16 + l];                    // self loop
        float2 f0 = __half22float2(*reinterpret_cast<__half2*>(&u.x));
        float2 f1 = __half22float2(*reinterpret_cast<__half2*>(&u.y));
        float2 f2 = __half22float2(*reinterpret_cast<__half2*>(&u.z));
        float2 f3 = __half22float2(*reinterpret_cast<__half2*>(&u.w));
        __half2 o0 = __floats2half2_rn((a0 + f0.x) * di, (a1 + f0.y) * di);
        __half2 o1 = __floats2half2_rn((a2 + f1.x) * di, (a3 + f1.y) * di);
        __half2 o2 = __floats2half2_rn((a4 + f2.x) * di, (a5 + f2.y) * di);
        __half2 o3 = __floats2half2_rn((a6 + f3.x) * di, (a7 + f3.y) * di);
        uint4 st;
        st.x = *reinterpret_cast<unsigned*>(&o0);
        st.y = *reinterpret_cast<unsigned*>(&o1);
        st.z = *reinterpret_cast<unsigned*>(&o2);
        st.w = *reinterpret_cast<unsigned*>(&o3);
        *reinterpret_cast<uint4*>(&g_agg2h[w * HID + l * 8]) = st;
    }
}

// ---------------- 6b) overflow fallback for layer-2 agg (normally empty) ----------------
__global__ void k_ovf2() {
    int nov = min(g_ovcnt, OVMAX);
    int lane = threadIdx.x & 31;
    int warp = (blockIdx.x * 256 + threadIdx.x) >> 5;
    int nw   = (gridDim.x * 256) >> 5;
    const uint2* hv = reinterpret_cast<const uint2*>(g_h1h);
    for (int i = warp; i < nov; i += nw) {
        int2 e = g_ov[i];                            // (dst, src)
        float wgt = g_dinv[e.x];
        uint2 u = hv[e.y * 32 + lane];
        float2 ul = __half22float2(*reinterpret_cast<__half2*>(&u.x));
        float2 uh = __half22float2(*reinterpret_cast<__half2*>(&u.y));
        __half2 d0 = __floats2half2_rn(ul.x * wgt, ul.y * wgt);
        __half2 d1 = __floats2half2_rn(uh.x * wgt, uh.y * wgt);
        atomicAdd(reinterpret_cast<__half2*>(&g_agg2h[e.x * HID + lane * 4]),     d0);
        atomicAdd(reinterpret_cast<__half2*>(&g_agg2h[e.x * HID + lane * 4 + 2]), d1);
    }
}

// ---------------- 7) GEMM2: out = agg2h @ W2 + b2, 4x8 FFMA2, fp16 A staging ----------------
__global__ void __launch_bounds__(256) k_gemm2(const float* __restrict__ W2,
                                               const float* __restrict__ b2,
                                               float* __restrict__ out) {
    __shared__ float As[TILE * HID];     // 32 KB
    int tid  = threadIdx.x;
    int tcol = (tid & 15) * 8;
    int trow = (tid >> 4) * 4;
    int row0 = blockIdx.x * TILE;
    u64 bias[4];
    bias[0] = packf2(__ldg(&b2[tcol]),     __ldg(&b2[tcol + 1]));
    bias[1] = packf2(__ldg(&b2[tcol + 2]), __ldg(&b2[tcol + 3]));
    bias[2] = packf2(__ldg(&b2[tcol + 4]), __ldg(&b2[tcol + 5]));
    bias[3] = packf2(__ldg(&b2[tcol + 6]), __ldg(&b2[tcol + 7]));

    // load 64x128 fp16 A tile (1024 uint4, 4 per thread), convert to fp32 smem
    const uint4* av = reinterpret_cast<const uint4*>(g_agg2h);   // 8 halves / uint4
#pragma unroll
    for (int i = 0; i < 4; i++) {
        int idx = tid + i * 256;                     // uint4 index, < 1024
        int gr  = row0 + (idx >> 4);
        uint4 u = (gr < NN) ? av[gr * 16 + (idx & 15)] : make_uint4(0, 0, 0, 0);
        float2 f0 = __half22float2(*reinterpret_cast<__half2*>(&u.x));
        float2 f1 = __half22float2(*reinterpret_cast<__half2*>(&u.y));
        float2 f2 = __half22float2(*reinterpret_cast<__half2*>(&u.z));
        float2 f3 = __half22float2(*reinterpret_cast<__half2*>(&u.w));
        float* dst = &As[(idx >> 4) * HID + (idx & 15) * 8];
        reinterpret_cast<float4*>(dst)[0] = make_float4(f0.x, f0.y, f1.x, f1.y);
        reinterpret_cast<float4*>(dst)[1] = make_float4(f2.x, f2.y, f3.x, f3.y);
    }
    __syncthreads();

    u64 acc[4][4];
#pragma unroll
    for (int r = 0; r < 4; r++)
#pragma unroll
        for (int c = 0; c < 4; c++) acc[r][c] = bias[c];
#pragma unroll 4
    for (int k = 0; k < HID; k++) {
        ulonglong2 wa = __ldg(reinterpret_cast<const ulonglong2*>(&W2[k * HID + tcol]));
        ulonglong2 wb = __ldg(reinterpret_cast<const ulonglong2*>(&W2[k * HID + tcol + 4]));
#pragma unroll
        for (int r = 0; r < 4; r++) {
            u64 a = dup2(As[(trow + r) * HID + k]);
            ffma2(acc[r][0], a, wa.x); ffma2(acc[r][1], a, wa.y);
            ffma2(acc[r][2], a, wb.x); ffma2(acc[r][3], a, wb.y);
        }
    }
#pragma unroll
    for (int r = 0; r < 4; r++) {
        int gr = row0 + trow + r;
        if (gr < NN) {
            float2 p0 = unpackf2(acc[r][0]);
            float2 p1 = unpackf2(acc[r][1]);
            float2 p2 = unpackf2(acc[r][2]);
            float2 p3 = unpackf2(acc[r][3]);
            *reinterpret_cast<float4*>(&out[gr * HID + tcol])     = make_float4(p0.x, p0.y, p1.x, p1.y);
            *reinterpret_cast<float4*>(&out[gr * HID + tcol + 4]) = make_float4(p2.x, p2.y, p3.x, p3.y);
        }
    }
}

// ---------------- host launcher ----------------
extern "C" void kernel_launch(void* const* d_in, const int* in_sizes, int n_in,
                              void* d_out, int out_size) {
    const int*   ei  = (const int*)d_in[1];
    const float* emb = (const float*)d_in[2];
    const float* W1  = (const float*)d_in[3];
    const float* b1  = (const float*)d_in[4];
    const float* W2  = (const float*)d_in[5];
    const float* b2  = (const float*)d_in[6];
    float* out = (float*)d_out;

    const int NT = (NN + TILE - 1) / TILE;           // 782
    k_init       <<<(NN + 255) / 256, 256>>>();
    k_scatter    <<<(ER / 8 + 255) / 256, 256>>>(ei);
    k_dinv_scale <<<(NN * (EMB / 4) + 255) / 256, 256>>>(emb);
    k_agg_emb    <<<(NN * 32) / 256, 256>>>();
    k_ovf1       <<<2, 256>>>();
    k_gemm1      <<<NT, 256>>>(W1, b1);
    k_agg_h1     <<<(NN * 32) / 256, 256>>>();
    k_ovf2       <<<2, 256>>>();
    k_gemm2      <<<NT, 256>>>(W2, b2, out);
}

// round 17
// speedup vs baseline: 1.0381x; 1.0381x over previous
#include <cuda_runtime.h>
#include <cuda_fp16.h>

#define NN   50000
#define ER   1600000
#define EMB  32
#define HID  128
#define TILE 64
#define CAP  128          // bucket capacity per node (E[deg]=32, P(>128)~1e-40)
#define OVMAX 8192
#define FULL 0xffffffffu

typedef unsigned long long u64;

// ---- packed f32x2 helpers (sm_103a FFMA2 path, PTX-only) ----
__device__ __forceinline__ u64 dup2(float a) {
    u64 r; asm("mov.b64 %0, {%1, %1};" : "=l"(r) : "f"(a)); return r;
}
__device__ __forceinline__ u64 packf2(float a, float b) {
    u64 r; asm("mov.b64 %0, {%1, %2};" : "=l"(r) : "f"(a), "f"(b)); return r;
}
__device__ __forceinline__ void ffma2(u64& d, u64 a, u64 b) {
    asm("fma.rn.f32x2 %0, %1, %2, %0;" : "+l"(d) : "l"(a), "l"(b));
}
__device__ __forceinline__ float2 unpackf2(u64 v) {
    float2 r; asm("mov.b64 {%0, %1}, %2;" : "=f"(r.x), "=f"(r.y) : "l"(v)); return r;
}

// ---- PDL primitives (sm_90+) ----
__device__ __forceinline__ void pdl_signal() {
    asm volatile("griddepcontrol.launch_dependents;");
}
__device__ __forceinline__ void pdl_wait() {
    asm volatile("griddepcontrol.wait;" ::: "memory");
}

// ---------------- device scratch (static, no cudaMalloc; 16B-aligned for LDG.128) ----------------
// NOTE: zero-initialized at module load; gemm2 tail re-zeroes cursor/ovcnt each run.
__device__ int    g_cursor[NN];
__device__ float  g_dinv[NN];
__device__ __align__(16) int    g_col[NN * CAP];     // 25.6 MB direct buckets
__device__ int    g_ovcnt;
__device__ int2   g_ov[OVMAX];
__device__ __align__(16) __half g_xsh[NN * EMB];     //  3.2 MB  (fp16 dinv-scaled emb)
__device__ __align__(16) float  g_aggemb[NN * EMB];  //  6.4 MB
__device__ __align__(16) __half g_h1h[NN * HID];     // 12.8 MB  (fp16 dinv-scaled hidden)
__device__ __align__(16) __half g_agg2h[NN * HID];   // 12.8 MB  (fp16 layer-2 aggregate)

// ---------------- 1) direct-bucket scatter (8 edges/thread, MLP=8) ----------------
__global__ void k_scatter(const int* __restrict__ ei) {
    pdl_signal();
    int t = blockIdx.x * 256 + threadIdx.x;          // t < ER/8
    if (t >= ER / 8) return;
    int4 sa = reinterpret_cast<const int4*>(ei)[2 * t];
    int4 sb = reinterpret_cast<const int4*>(ei)[2 * t + 1];
    int4 da = reinterpret_cast<const int4*>(ei + ER)[2 * t];
    int4 db = reinterpret_cast<const int4*>(ei + ER)[2 * t + 1];
    int p0 = atomicAdd(&g_cursor[da.x], 1);
    int p1 = atomicAdd(&g_cursor[da.y], 1);
    int p2 = atomicAdd(&g_cursor[da.z], 1);
    int p3 = atomicAdd(&g_cursor[da.w], 1);
    int p4 = atomicAdd(&g_cursor[db.x], 1);
    int p5 = atomicAdd(&g_cursor[db.y], 1);
    int p6 = atomicAdd(&g_cursor[db.z], 1);
    int p7 = atomicAdd(&g_cursor[db.w], 1);
#define PUT(p, d, s) \
    if ((p) < CAP) g_col[(d) * CAP + (p)] = (s); \
    else { int o = atomicAdd(&g_ovcnt, 1); if (o < OVMAX) g_ov[o] = make_int2((d), (s)); }
    PUT(p0, da.x, sa.x) PUT(p1, da.y, sa.y) PUT(p2, da.z, sa.z) PUT(p3, da.w, sa.w)
    PUT(p4, db.x, sb.x) PUT(p5, db.y, sb.y) PUT(p6, db.z, sb.z) PUT(p7, db.w, sb.w)
#undef PUT
}

// ---------------- 2) fused dinv + xsh = fp16(dinv * emb) ----------------
__global__ void k_dinv_scale(const float* __restrict__ emb) {
    pdl_signal();
    int t = blockIdx.x * 256 + threadIdx.x;          // t < NN*8 (float4 per thread)
    if (t >= NN * (EMB / 4)) return;
    int n = t >> 3;
    float4 v = reinterpret_cast<const float4*>(emb)[t];   // independent of scatter
    pdl_wait();                                           // cursor now final
    float d = rsqrtf((float)(g_cursor[n] + 1));      // +1 self loop
    if ((t & 7) == 0) g_dinv[n] = d;
    __half2 h0 = __floats2half2_rn(v.x * d, v.y * d);
    __half2 h1 = __floats2half2_rn(v.z * d, v.w * d);
    uint2 st;
    st.x = *reinterpret_cast<unsigned*>(&h0);
    st.y = *reinterpret_cast<unsigned*>(&h1);
    reinterpret_cast<uint2*>(g_xsh)[t] = st;
}

// ---------------- 3) aggregate embeddings: fp16 HADD2 accumulate + inline ovf ----------------
// lane = 4*g + l : group g in [0,8) handles edge jb+g; sublane l in [0,4) owns dims [8l, 8l+8).
__global__ void __launch_bounds__(256) k_agg_emb() {
    pdl_signal();
    int w    = (blockIdx.x * 256 + threadIdx.x) >> 5;
    int lane = threadIdx.x & 31;
    int g    = lane >> 2;
    int l    = lane & 3;
    pdl_wait();
    float di = g_dinv[w];
    float a0 = 0.f, a1 = 0.f, a2 = 0.f, a3 = 0.f,
          a4 = 0.f, a5 = 0.f, a6 = 0.f, a7 = 0.f;
    int cntRaw = g_cursor[w];
    int cnt = min(cntRaw, CAP);
    const int* cb = g_col + w * CAP;
    const uint4* xv = reinterpret_cast<const uint4*>(g_xsh);   // 8 halves / uint4, 4 per row
    const __half2 hz = __float2half2_rn(0.f);
    for (int base = 0; base < cnt; base += 32) {
        int c = cb[base + lane];                     // coalesced 128B
        int m = min(32, cnt - base);                 // warp-uniform
        __half2 h0 = hz, h1 = hz, h2 = hz, h3 = hz;  // <=4-term fp16 chains
        if (m == 32) {
#pragma unroll
            for (int jb = 0; jb < 32; jb += 8) {
                int   s = __shfl_sync(FULL, c, jb + g);        // per-lane source
                uint4 u = xv[s * 4 + l];
                h0 = __hadd2(h0, *reinterpret_cast<__half2*>(&u.x));
                h1 = __hadd2(h1, *reinterpret_cast<__half2*>(&u.y));
                h2 = __hadd2(h2, *reinterpret_cast<__half2*>(&u.z));
                h3 = __hadd2(h3, *reinterpret_cast<__half2*>(&u.w));
            }
        } else {
            for (int jb = 0; jb < m; jb += 8) {
                int  j   = jb + g;
                bool act = (j < m);
                int  s   = __shfl_sync(FULL, c, act ? j : 0);
                uint4 u  = xv[s * 4 + l];
                if (act) {
                    h0 = __hadd2(h0, *reinterpret_cast<__half2*>(&u.x));
                    h1 = __hadd2(h1, *reinterpret_cast<__half2*>(&u.y));
                    h2 = __hadd2(h2, *reinterpret_cast<__half2*>(&u.z));
                    h3 = __hadd2(h3, *reinterpret_cast<__half2*>(&u.w));
                }
            }
        }
        float2 f0 = __half22float2(h0);
        float2 f1 = __half22float2(h1);
        float2 f2 = __half22float2(h2);
        float2 f3 = __half22float2(h3);
        a0 += f0.x; a1 += f0.y; a2 += f1.x; a3 += f1.y;
        a4 += f2.x; a5 += f2.y; a6 += f3.x; a7 += f3.y;
    }
    // reduce across the 8 groups (lanes differing in bits 2,3,4)
#pragma unroll
    for (int off = 4; off <= 16; off <<= 1) {
        a0 += __shfl_xor_sync(FULL, a0, off);
        a1 += __shfl_xor_sync(FULL, a1, off);
        a2 += __shfl_xor_sync(FULL, a2, off);
        a3 += __shfl_xor_sync(FULL, a3, off);
        a4 += __shfl_xor_sync(FULL, a4, off);
        a5 += __shfl_xor_sync(FULL, a5, off);
        a6 += __shfl_xor_sync(FULL, a6, off);
        a7 += __shfl_xor_sync(FULL, a7, off);
    }
    if (g == 0) {
        // inline overflow handling (astronomically rare; loop empty in practice)
        if (cntRaw > CAP) {
            int nov = min(g_ovcnt, OVMAX);
            for (int i = 0; i < nov; i++) {
                int2 e = g_ov[i];
                if (e.x == w) {
                    uint4 u = xv[e.y * 4 + l];
                    float2 q0 = __half22float2(*reinterpret_cast<__half2*>(&u.x));
                    float2 q1 = __half22float2(*reinterpret_cast<__half2*>(&u.y));
                    float2 q2 = __half22float2(*reinterpret_cast<__half2*>(&u.z));
                    float2 q3 = __half22float2(*reinterpret_cast<__half2*>(&u.w));
                    a0 += q0.x; a1 += q0.y; a2 += q1.x; a3 += q1.y;
                    a4 += q2.x; a5 += q2.y; a6 += q3.x; a7 += q3.y;
                }
            }
        }
        uint4 u = xv[w * 4 + l];                     // self loop
        float2 f0 = __half22float2(*reinterpret_cast<__half2*>(&u.x));
        float2 f1 = __half22float2(*reinterpret_cast<__half2*>(&u.y));
        float2 f2 = __half22float2(*reinterpret_cast<__half2*>(&u.z));
        float2 f3 = __half22float2(*reinterpret_cast<__half2*>(&u.w));
        a0 = (a0 + f0.x) * di; a1 = (a1 + f0.y) * di;
        a2 = (a2 + f1.x) * di; a3 = (a3 + f1.y) * di;
        a4 = (a4 + f2.x) * di; a5 = (a5 + f2.y) * di;
        a6 = (a6 + f3.x) * di; a7 = (a7 + f3.y) * di;
        float4* dst = reinterpret_cast<float4*>(&g_aggemb[w * EMB + l * 8]);
        dst[0] = make_float4(a0, a1, a2, a3);
        dst[1] = make_float4(a4, a5, a6, a7);
    }
}

// ---------------- 4) GEMM1: h1s = dinv * relu(aggemb @ W1 + b1) -> fp16 ----------------
__global__ void __launch_bounds__(256) k_gemm1(const float* __restrict__ W1,
                                               const float* __restrict__ b1) {
    pdl_signal();
    __shared__ float As[TILE * EMB];     // 8 KB
    int tid  = threadIdx.x;
    int tcol = (tid & 15) * 8;
    int trow = (tid >> 4) * 4;
    int row0 = blockIdx.x * TILE;
    u64 bias[4];                          // independent of predecessor
    bias[0] = packf2(__ldg(&b1[tcol]),     __ldg(&b1[tcol + 1]));
    bias[1] = packf2(__ldg(&b1[tcol + 2]), __ldg(&b1[tcol + 3]));
    bias[2] = packf2(__ldg(&b1[tcol + 4]), __ldg(&b1[tcol + 5]));
    bias[3] = packf2(__ldg(&b1[tcol + 6]), __ldg(&b1[tcol + 7]));
    pdl_wait();

#pragma unroll
    for (int i = 0; i < 2; i++) {
        int idx = tid + i * 256;
        int gr  = row0 + (idx >> 3);
        reinterpret_cast<float4*>(As)[idx] = (gr < NN)
            ? reinterpret_cast<const float4*>(g_aggemb)[gr * 8 + (idx & 7)]
            : make_float4(0.f, 0.f, 0.f, 0.f);
    }
    __syncthreads();

    u64 acc[4][4];
#pragma unroll
    for (int r = 0; r < 4; r++)
#pragma unroll
        for (int c = 0; c < 4; c++) acc[r][c] = bias[c];
#pragma unroll
    for (int k = 0; k < EMB; k++) {
        ulonglong2 wa = __ldg(reinterpret_cast<const ulonglong2*>(&W1[k * HID + tcol]));
        ulonglong2 wb = __ldg(reinterpret_cast<const ulonglong2*>(&W1[k * HID + tcol + 4]));
#pragma unroll
        for (int r = 0; r < 4; r++) {
            u64 a = dup2(As[(trow + r) * EMB + k]);
            ffma2(acc[r][0], a, wa.x); ffma2(acc[r][1], a, wa.y);
            ffma2(acc[r][2], a, wb.x); ffma2(acc[r][3], a, wb.y);
        }
    }
#pragma unroll
    for (int r = 0; r < 4; r++) {
        int gr = row0 + trow + r;
        if (gr < NN) {
            float d = g_dinv[gr];
            float2 p0 = unpackf2(acc[r][0]);
            float2 p1 = unpackf2(acc[r][1]);
            float2 p2 = unpackf2(acc[r][2]);
            float2 p3 = unpackf2(acc[r][3]);
            __half2 h0 = __floats2half2_rn(fmaxf(p0.x, 0.f) * d, fmaxf(p0.y, 0.f) * d);
            __half2 h1 = __floats2half2_rn(fmaxf(p1.x, 0.f) * d, fmaxf(p1.y, 0.f) * d);
            __half2 h2 = __floats2half2_rn(fmaxf(p2.x, 0.f) * d, fmaxf(p2.y, 0.f) * d);
            __half2 h3 = __floats2half2_rn(fmaxf(p3.x, 0.f) * d, fmaxf(p3.y, 0.f) * d);
            uint4 st;
            st.x = *reinterpret_cast<unsigned*>(&h0);
            st.y = *reinterpret_cast<unsigned*>(&h1);
            st.z = *reinterpret_cast<unsigned*>(&h2);
            st.w = *reinterpret_cast<unsigned*>(&h3);
            *reinterpret_cast<uint4*>(&g_h1h[gr * HID + tcol]) = st;
        }
    }
}

// ---------------- 5) aggregate h1s: fp16 gather, fp32 accum, 2 edges in flight + inline ovf ----------------
// lane = 16*g + l : group g handles edge jb+g; sublane l owns dims [8l, 8l+8).
__global__ void __launch_bounds__(256) k_agg_h1() {
    pdl_signal();
    int w    = (blockIdx.x * 256 + threadIdx.x) >> 5;
    int lane = threadIdx.x & 31;
    int g    = lane >> 4;
    int l    = lane & 15;
    pdl_wait();
    float di = g_dinv[w];
    float a0 = 0.f, a1 = 0.f, a2 = 0.f, a3 = 0.f,
          a4 = 0.f, a5 = 0.f, a6 = 0.f, a7 = 0.f;
    int cntRaw = g_cursor[w];
    int cnt = min(cntRaw, CAP);
    const int* cb = g_col + w * CAP;
    const uint4* hv = reinterpret_cast<const uint4*>(g_h1h);   // 8 halves / uint4
    for (int base = 0; base < cnt; base += 32) {
        int c = cb[base + lane];
        int m = min(32, cnt - base);                 // warp-uniform
        if (m == 32) {
#pragma unroll 4
            for (int jb = 0; jb < 32; jb += 2) {
                int   s = __shfl_sync(FULL, c, jb + g);
                uint4 u = hv[s * 16 + l];
                float2 f0 = __half22float2(*reinterpret_cast<__half2*>(&u.x));
                float2 f1 = __half22float2(*reinterpret_cast<__half2*>(&u.y));
                float2 f2 = __half22float2(*reinterpret_cast<__half2*>(&u.z));
                float2 f3 = __half22float2(*reinterpret_cast<__half2*>(&u.w));
                a0 += f0.x; a1 += f0.y; a2 += f1.x; a3 += f1.y;
                a4 += f2.x; a5 += f2.y; a6 += f3.x; a7 += f3.y;
            }
        } else {
            for (int jb = 0; jb < m; jb += 2) {
                int  j   = jb + g;
                bool act = (j < m);
                int  s   = __shfl_sync(FULL, c, act ? j : 0);
                uint4 u  = hv[s * 16 + l];
                float2 f0 = __half22float2(*reinterpret_cast<__half2*>(&u.x));
                float2 f1 = __half22float2(*reinterpret_cast<__half2*>(&u.y));
                float2 f2 = __half22float2(*reinterpret_cast<__half2*>(&u.z));
                float2 f3 = __half22float2(*reinterpret_cast<__half2*>(&u.w));
                if (act) {
                    a0 += f0.x; a1 += f0.y; a2 += f1.x; a3 += f1.y;
                    a4 += f2.x; a5 += f2.y; a6 += f3.x; a7 += f3.y;
                }
            }
        }
    }
    a0 += __shfl_xor_sync(FULL, a0, 16);
    a1 += __shfl_xor_sync(FULL, a1, 16);
    a2 += __shfl_xor_sync(FULL, a2, 16);
    a3 += __shfl_xor_sync(FULL, a3, 16);
    a4 += __shfl_xor_sync(FULL, a4, 16);
    a5 += __shfl_xor_sync(FULL, a5, 16);
    a6 += __shfl_xor_sync(FULL, a6, 16);
    a7 += __shfl_xor_sync(FULL, a7, 16);
    if (g == 0) {
        if (cntRaw > CAP) {                          // inline overflow (rare)
            int nov = min(g_ovcnt, OVMAX);
            for (int i = 0; i < nov; i++) {
                int2 e = g_ov[i];
                if (e.x == w) {
                    uint4 u = hv[e.y * 16 + l];
                    float2 q0 = __half22float2(*reinterpret_cast<__half2*>(&u.x));
                    float2 q1 = __half22float2(*reinterpret_cast<__half2*>(&u.y));
                    float2 q2 = __half22float2(*reinterpret_cast<__half2*>(&u.z));
                    float2 q3 = __half22float2(*reinterpret_cast<__half2*>(&u.w));
                    a0 += q0.x; a1 += q0.y; a2 += q1.x; a3 += q1.y;
                    a4 += q2.x; a5 += q2.y; a6 += q3.x; a7 += q3.y;
                }
            }
        }
        uint4 u = hv[w * 16 + l];                    // self loop
        float2 f0 = __half22float2(*reinterpret_cast<__half2*>(&u.x));
        float2 f1 = __half22float2(*reinterpret_cast<__half2*>(&u.y));
        float2 f2 = __half22float2(*reinterpret_cast<__half2*>(&u.z));
        float2 f3 = __half22float2(*reinterpret_cast<__half2*>(&u.w));
        __half2 o0 = __floats2half2_rn((a0 + f0.x) * di, (a1 + f0.y) * di);
        __half2 o1 = __floats2half2_rn((a2 + f1.x) * di, (a3 + f1.y) * di);
        __half2 o2 = __floats2half2_rn((a4 + f2.x) * di, (a5 + f2.y) * di);
        __half2 o3 = __floats2half2_rn((a6 + f3.x) * di, (a7 + f3.y) * di);
        uint4 st;
        st.x = *reinterpret_cast<unsigned*>(&o0);
        st.y = *reinterpret_cast<unsigned*>(&o1);
        st.z = *reinterpret_cast<unsigned*>(&o2);
        st.w = *reinterpret_cast<unsigned*>(&o3);
        *reinterpret_cast<uint4*>(&g_agg2h[w * HID + l * 8]) = st;
    }
}

// ---------------- 6) GEMM2: out = agg2h @ W2 + b2 + self-clean tail ----------------
__global__ void __launch_bounds__(256) k_gemm2(const float* __restrict__ W2,
                                               const float* __restrict__ b2,
                                               float* __restrict__ out) {
    __shared__ float As[TILE * HID];     // 32 KB
    int tid  = threadIdx.x;
    int tcol = (tid & 15) * 8;
    int trow = (tid >> 4) * 4;
    int row0 = blockIdx.x * TILE;
    u64 bias[4];                          // independent of predecessor
    bias[0] = packf2(__ldg(&b2[tcol]),     __ldg(&b2[tcol + 1]));
    bias[1] = packf2(__ldg(&b2[tcol + 2]), __ldg(&b2[tcol + 3]));
    bias[2] = packf2(__ldg(&b2[tcol + 4]), __ldg(&b2[tcol + 5]));
    bias[3] = packf2(__ldg(&b2[tcol + 6]), __ldg(&b2[tcol + 7]));
    pdl_wait();

    // load 64x128 fp16 A tile (1024 uint4, 4 per thread), convert to fp32 smem
    const uint4* av = reinterpret_cast<const uint4*>(g_agg2h);   // 8 halves / uint4
#pragma unroll
    for (int i = 0; i < 4; i++) {
        int idx = tid + i * 256;                     // uint4 index, < 1024
        int gr  = row0 + (idx >> 4);
        uint4 u = (gr < NN) ? av[gr * 16 + (idx & 15)] : make_uint4(0, 0, 0, 0);
        float2 f0 = __half22float2(*reinterpret_cast<__half2*>(&u.x));
        float2 f1 = __half22float2(*reinterpret_cast<__half2*>(&u.y));
        float2 f2 = __half22float2(*reinterpret_cast<__half2*>(&u.z));
        float2 f3 = __half22float2(*reinterpret_cast<__half2*>(&u.w));
        float* dst = &As[(idx >> 4) * HID + (idx & 15) * 8];
        reinterpret_cast<float4*>(dst)[0] = make_float4(f0.x, f0.y, f1.x, f1.y);
        reinterpret_cast<float4*>(dst)[1] = make_float4(f2.x, f2.y, f3.x, f3.y);
    }
    // self-clean for next graph replay: zero this tile's cursors (+ ovcnt once)
    if (tid < TILE) {
        int gr = row0 + tid;
        if (gr < NN) g_cursor[gr] = 0;
    }
    if (blockIdx.x == 0 && tid == 0) g_ovcnt = 0;
    __syncthreads();

    u64 acc[4][4];
#pragma unroll
    for (int r = 0; r < 4; r++)
#pragma unroll
        for (int c = 0; c < 4; c++) acc[r][c] = bias[c];
#pragma unroll 4
    for (int k = 0; k < HID; k++) {
        ulonglong2 wa = __ldg(reinterpret_cast<const ulonglong2*>(&W2[k * HID + tcol]));
        ulonglong2 wb = __ldg(reinterpret_cast<const ulonglong2*>(&W2[k * HID + tcol + 4]));
#pragma unroll
        for (int r = 0; r < 4; r++) {
            u64 a = dup2(As[(trow + r) * HID + k]);
            ffma2(acc[r][0], a, wa.x); ffma2(acc[r][1], a, wa.y);
            ffma2(acc[r][2], a, wb.x); ffma2(acc[r][3], a, wb.y);
        }
    }
#pragma unroll
    for (int r = 0; r < 4; r++) {
        int gr = row0 + trow + r;
        if (gr < NN) {
            float2 p0 = unpackf2(acc[r][0]);
            float2 p1 = unpackf2(acc[r][1]);
            float2 p2 = unpackf2(acc[r][2]);
            float2 p3 = unpackf2(acc[r][3]);
            *reinterpret_cast<float4*>(&out[gr * HID + tcol])     = make_float4(p0.x, p0.y, p1.x, p1.y);
            *reinterpret_cast<float4*>(&out[gr * HID + tcol + 4]) = make_float4(p2.x, p2.y, p3.x, p3.y);
        }
    }
}

// ---------------- host launcher: PDL chain ----------------
template <typename F, typename... Args>
static void launch_pdl(F f, unsigned grid, unsigned block, Args... args) {
    cudaLaunchConfig_t cfg = {};
    cfg.gridDim  = {grid, 1, 1};
    cfg.blockDim = {block, 1, 1};
    cfg.stream   = 0;
    cudaLaunchAttribute at[1];
    at[0].id = cudaLaunchAttributeProgrammaticStreamSerialization;
    at[0].val.programmaticStreamSerializationAllowed = 1;
    cfg.attrs = at;
    cfg.numAttrs = 1;
    cudaLaunchKernelEx(&cfg, f, args...);
}

extern "C" void kernel_launch(void* const* d_in, const int* in_sizes, int n_in,
                              void* d_out, int out_size) {
    const int*   ei  = (const int*)d_in[1];
    const float* emb = (const float*)d_in[2];
    const float* W1  = (const float*)d_in[3];
    const float* b1  = (const float*)d_in[4];
    const float* W2  = (const float*)d_in[5];
    const float* b2  = (const float*)d_in[6];
    float* out = (float*)d_out;

    const unsigned NT = (NN + TILE - 1) / TILE;      // 782
    k_scatter<<<(ER / 8 + 255) / 256, 256>>>(ei);    // first in chain: plain launch
    launch_pdl(k_dinv_scale, (NN * (EMB / 4) + 255) / 256, 256, emb);
    launch_pdl(k_agg_emb,    (NN * 32) / 256, 256);
    launch_pdl(k_gemm1,      NT, 256, W1, b1);
    launch_pdl(k_agg_h1,     (NN * 32) / 256, 256);
    launch_pdl(k_gemm2,      NT, 256, W2, b2, out);
}